// round 7
// baseline (speedup 1.0000x reference)
#include <cuda_runtime.h>
#include <cuda_bf16.h>
#include <cstdint>

// Problem constants
#define SEQ   2048
#define BATCH 64
#define FEAT  64
#define HID   256
#define NLAY  2

typedef unsigned long long ull;

// ---------------------------------------------------------------------------
// Device scratch (no allocations allowed)
// ---------------------------------------------------------------------------
__device__ float g_X0[SEQ * BATCH * HID];   // encoder output
__device__ float g_X1[SEQ * BATCH * HID];   // layer0 output
__device__ float g_X2[SEQ * BATCH * HID];   // layer1 output
__device__ float g_Hbuf[NLAY * 2 * BATCH * HID]; // [layer][buf][b*HID + j]
__device__ unsigned g_cnt[NLAY];            // per-layer-group step counters

// ---------------------------------------------------------------------------
// Helpers
// ---------------------------------------------------------------------------
__device__ __forceinline__ ull ffma2(ull a, ull b, ull c) {
    ull d;
    asm("fma.rn.f32x2 %0, %1, %2, %3;" : "=l"(d) : "l"(a), "l"(b), "l"(c));
    return d;
}
__device__ __forceinline__ float sumpair(ull v) {
    float lo, hi;
    asm("mov.b64 {%0, %1}, %2;" : "=f"(lo), "=f"(hi) : "l"(v));
    return lo + hi;
}
__device__ __forceinline__ float sigm(float x) {
    return 1.0f / (1.0f + __expf(-x));
}
__device__ __forceinline__ float tanh_fast(float x) {
    float ax = fabsf(x);
    float t  = __expf(-2.0f * ax);
    float r  = (1.0f - t) / (1.0f + t);
    return copysignf(r, x);
}
__device__ __forceinline__ void cp16(void* dst_smem, const void* src) {
    unsigned d = (unsigned)__cvta_generic_to_shared(dst_smem);
    asm volatile("cp.async.cg.shared.global [%0], [%1], 16;" :: "r"(d), "l"(src));
}

// ---------------------------------------------------------------------------
// Init kernel: zero h buffers + barrier counters (runs every launch/replay)
// ---------------------------------------------------------------------------
__global__ void init_kernel() {
    int idx = blockIdx.x * blockDim.x + threadIdx.x;
    if (idx < NLAY) g_cnt[idx] = 0u;
    int stride = gridDim.x * blockDim.x;
    for (int i = idx; i < NLAY * 2 * BATCH * HID; i += stride) g_Hbuf[i] = 0.0f;
}

// ---------------------------------------------------------------------------
// Generic GEMM + bias:  C[M,N] = A[M,K] @ Bw[N,K]^T + bias[N]
//   BM=64, BN=32, BK=32, 128 threads, 4x4 microtiles
// ---------------------------------------------------------------------------
__global__ void __launch_bounds__(128) gemm_bias_kernel(
    const float* __restrict__ A, const float* __restrict__ Bw,
    const float* __restrict__ bias, float* __restrict__ C,
    int M, int N, int K)
{
    __shared__ float As[32][64 + 4];
    __shared__ float Bs[32][32 + 4];

    const int m0 = blockIdx.x * 64;
    const int n0 = blockIdx.y * 32;
    const int tid = threadIdx.x;
    const int tm = tid & 15;   // 16 groups of 4 rows
    const int tn = tid >> 4;   // 8 groups of 4 cols

    float acc[4][4];
#pragma unroll
    for (int i = 0; i < 4; i++)
#pragma unroll
        for (int jj = 0; jj < 4; jj++) acc[i][jj] = 0.0f;

    for (int kc = 0; kc < K; kc += 32) {
        // A tile 64x32 (512 float4, 4 per thread), transpose into As[k][m]
#pragma unroll
        for (int i = 0; i < 4; i++) {
            int idx = tid + i * 128;
            int r = idx >> 3, c4 = idx & 7;
            float4 v = *(const float4*)(A + (size_t)(m0 + r) * K + kc + c4 * 4);
            As[c4 * 4 + 0][r] = v.x;
            As[c4 * 4 + 1][r] = v.y;
            As[c4 * 4 + 2][r] = v.z;
            As[c4 * 4 + 3][r] = v.w;
        }
        // B tile 32x32 (256 float4, 2 per thread) into Bs[k][n]
#pragma unroll
        for (int i = 0; i < 2; i++) {
            int idx = tid + i * 128;
            int r = idx >> 3, c4 = idx & 7;
            float4 v = *(const float4*)(Bw + (size_t)(n0 + r) * K + kc + c4 * 4);
            Bs[c4 * 4 + 0][r] = v.x;
            Bs[c4 * 4 + 1][r] = v.y;
            Bs[c4 * 4 + 2][r] = v.z;
            Bs[c4 * 4 + 3][r] = v.w;
        }
        __syncthreads();

#pragma unroll
        for (int kk = 0; kk < 32; ++kk) {
            float4 a = *(const float4*)&As[kk][tm * 4];
            float4 b = *(const float4*)&Bs[kk][tn * 4];
            float av[4] = {a.x, a.y, a.z, a.w};
            float bv[4] = {b.x, b.y, b.z, b.w};
#pragma unroll
            for (int i = 0; i < 4; i++)
#pragma unroll
                for (int jj = 0; jj < 4; jj++)
                    acc[i][jj] = fmaf(av[i], bv[jj], acc[i][jj]);
        }
        __syncthreads();
    }

    float b0v = bias[n0 + tn * 4 + 0];
    float b1v = bias[n0 + tn * 4 + 1];
    float b2v = bias[n0 + tn * 4 + 2];
    float b3v = bias[n0 + tn * 4 + 3];
#pragma unroll
    for (int i = 0; i < 4; i++) {
        float4 o;
        o.x = acc[i][0] + b0v;
        o.y = acc[i][1] + b1v;
        o.z = acc[i][2] + b2v;
        o.w = acc[i][3] + b3v;
        *(float4*)(C + (size_t)(m0 + tm * 4 + i) * N + n0 + tn * 4) = o;
    }
}

// ---------------------------------------------------------------------------
// Persistent pipelined 2-layer LSTM kernel.
// Grid = 128 CTAs: CTAs [0,64) = layer 0, [64,128) = layer 1.
// Per CTA: tile 8 hidden-units x 32 batches, all 4 gates, K = 512 ([x_t ; h]).
// SMEM: sW = 16384 floats (W reshuffled [k4][g][j][4]),
//       sU = 32 rows x 524 floats ([b][k], padded for bank spread).
// Per thread (128): (j = tid&7, 2 batches = 2*(tid>>3)+{0,1}); 8 f32x2
// accumulators packed over k-pairs; cell state c held in registers for all
// 2048 steps. Group barrier = monotone global counter; layer1 additionally
// gates each step on layer0's counter (wavefront pipeline).
// ---------------------------------------------------------------------------
#define U_STRIDE 524
#define LSTM_SMEM_FLOATS (16384 + 32 * U_STRIDE)

__global__ void __launch_bounds__(128, 1) lstm_kernel(
    const float* __restrict__ w_ih, const float* __restrict__ w_hh,
    const float* __restrict__ b_ih, const float* __restrict__ b_hh)
{
    extern __shared__ float smem[];
    float* sW = smem;             // 16384 floats
    float* sU = smem + 16384;     // 32 * 524 floats

    const int layer = blockIdx.x >> 6;
    const int c     = blockIdx.x & 63;
    const int j0    = (c & 31) * 8;   // 32 j-blocks of 8
    const int b0    = (c >> 5) * 32;  // 2 b-blocks of 32
    const int tid   = threadIdx.x;
    const int j     = tid & 7;
    const int bt    = tid >> 3;
    const int bLa   = bt * 2;
    const int bLb   = bt * 2 + 1;

    const float* Xin  = layer ? g_X1 : g_X0;
    float*       Xout = layer ? g_X2 : g_X1;
    float*       Hb   = g_Hbuf + (size_t)layer * (2 * BATCH * HID);

    // ---- Load & reshuffle W once: dest layout [k4][g][j][4] ----
    for (int idx = tid; idx < 16384; idx += 128) {
        int kk = idx & 3;
        int jj = (idx >> 2) & 7;
        int g  = (idx >> 5) & 3;
        int k4 = idx >> 7;
        int k  = k4 * 4 + kk;
        int r  = g * 256 + j0 + jj;
        float v = (k < 256)
            ? w_ih[((size_t)layer * 1024 + r) * 256 + k]
            : w_hh[((size_t)layer * 1024 + r) * 256 + (k - 256)];
        sW[idx] = v;
    }

    const int jg = j0 + j;
    // b_ih / b_hh shape: (NLAY, 4*HID) -> layer stride is 1024 (FIXED)
    const float Bi = b_ih[layer * 1024 + 0 * 256 + jg] + b_hh[layer * 1024 + 0 * 256 + jg];
    const float Bf = b_ih[layer * 1024 + 1 * 256 + jg] + b_hh[layer * 1024 + 1 * 256 + jg];
    const float Bg = b_ih[layer * 1024 + 2 * 256 + jg] + b_hh[layer * 1024 + 2 * 256 + jg];
    const float Bo = b_ih[layer * 1024 + 3 * 256 + jg] + b_hh[layer * 1024 + 3 * 256 + jg];

    float cA = 0.0f, cB = 0.0f;
    __syncthreads();  // W ready

    for (int t = 0; t < SEQ; ++t) {
        // ---- wait: own group finished step t-1; layer1 also needs x_t ----
        if (tid == 0) {
            volatile unsigned* cs = &g_cnt[layer];
            unsigned tgt = 64u * (unsigned)t;
            while (*cs < tgt) __nanosleep(40);
            if (layer) {
                volatile unsigned* c0 = &g_cnt[0];
                unsigned tx = 64u * (unsigned)(t + 1);
                while (*c0 < tx) __nanosleep(40);
            }
            __threadfence();
        }
        __syncthreads();

        // ---- stage U = [x_t ; h_{t-1}] for our 32 batches via cp.async ----
        const float* Hprev = Hb + (size_t)((t + 1) & 1) * (BATCH * HID);
#pragma unroll
        for (int i = 0; i < 32; ++i) {
            int idx = tid + i * 128;      // 0..4095 float4 slots
            int bl  = idx >> 7;           // 0..31
            int k4  = idx & 127;          // 0..127
            float* dst = sU + bl * U_STRIDE + k4 * 4;
            const float* src = (k4 < 64)
                ? (Xin + ((size_t)t * BATCH + b0 + bl) * HID + k4 * 4)
                : (Hprev + (size_t)(b0 + bl) * HID + (k4 - 64) * 4);
            cp16(dst, src);
        }
        asm volatile("cp.async.commit_group;\n" ::: "memory");
        asm volatile("cp.async.wait_group 0;\n" ::: "memory");
        __syncthreads();

        // ---- compute: 4 gates x 2 batches, K=512, f32x2 over k-pairs ----
        ull aI = 0, aF = 0, aG = 0, aO = 0;
        ull bI = 0, bF = 0, bG = 0, bO = 0;
        const float* UA = sU + bLa * U_STRIDE;
        const float* UB = sU + bLb * U_STRIDE;
        const ulonglong2* Wq = (const ulonglong2*)sW;

#pragma unroll 8
        for (int k4 = 0; k4 < 128; ++k4) {
            ulonglong2 ua = *(const ulonglong2*)(UA + k4 * 4);
            ulonglong2 ub = *(const ulonglong2*)(UB + k4 * 4);
            int wb = k4 * 32 + j;  // float4/ulonglong2 index of gate-i row
            ulonglong2 wi = Wq[wb];
            ulonglong2 wf = Wq[wb + 8];
            ulonglong2 wg = Wq[wb + 16];
            ulonglong2 wo = Wq[wb + 24];
            aI = ffma2(ua.x, wi.x, aI); aI = ffma2(ua.y, wi.y, aI);
            bI = ffma2(ub.x, wi.x, bI); bI = ffma2(ub.y, wi.y, bI);
            aF = ffma2(ua.x, wf.x, aF); aF = ffma2(ua.y, wf.y, aF);
            bF = ffma2(ub.x, wf.x, bF); bF = ffma2(ub.y, wf.y, bF);
            aG = ffma2(ua.x, wg.x, aG); aG = ffma2(ua.y, wg.y, aG);
            bG = ffma2(ub.x, wg.x, bG); bG = ffma2(ub.y, wg.y, bG);
            aO = ffma2(ua.x, wo.x, aO); aO = ffma2(ua.y, wo.y, aO);
            bO = ffma2(ub.x, wo.x, bO); bO = ffma2(ub.y, wo.y, bO);
        }

        // ---- epilogue: activations + state update + h writes ----
        {
            float iv = sigm(sumpair(aI) + Bi);
            float fv = sigm(sumpair(aF) + Bf);
            float gv = tanh_fast(sumpair(aG) + Bg);
            float ov = sigm(sumpair(aO) + Bo);
            cA = fv * cA + iv * gv;
            float hA = ov * tanh_fast(cA);

            float iv2 = sigm(sumpair(bI) + Bi);
            float fv2 = sigm(sumpair(bF) + Bf);
            float gv2 = tanh_fast(sumpair(bG) + Bg);
            float ov2 = sigm(sumpair(bO) + Bo);
            cB = fv2 * cB + iv2 * gv2;
            float hB = ov2 * tanh_fast(cB);

            float* Hcur = Hb + (size_t)(t & 1) * (BATCH * HID);
            Hcur[(size_t)(b0 + bLa) * HID + jg] = hA;
            Hcur[(size_t)(b0 + bLb) * HID + jg] = hB;
            Xout[((size_t)t * BATCH + b0 + bLa) * HID + jg] = hA;
            Xout[((size_t)t * BATCH + b0 + bLb) * HID + jg] = hB;
        }

        __threadfence();
        __syncthreads();
        if (tid == 0) atomicAdd(&g_cnt[layer], 1u);
    }
}

// ---------------------------------------------------------------------------
// Launch
// ---------------------------------------------------------------------------
extern "C" void kernel_launch(void* const* d_in, const int* in_sizes, int n_in,
                              void* d_out, int out_size)
{
    const float* input_ids = (const float*)d_in[0];
    const float* enc_w     = (const float*)d_in[1];
    const float* enc_b     = (const float*)d_in[2];
    const float* w_ih      = (const float*)d_in[3];
    const float* w_hh      = (const float*)d_in[4];
    const float* b_ih      = (const float*)d_in[5];
    const float* b_hh      = (const float*)d_in[6];
    const float* dec_w     = (const float*)d_in[7];
    const float* dec_b     = (const float*)d_in[8];
    float* out = (float*)d_out;

    void *p0, *p2;
    cudaGetSymbolAddress(&p0, g_X0);
    cudaGetSymbolAddress(&p2, g_X2);
    float* X0 = (float*)p0;
    float* X2 = (float*)p2;

    const int M = SEQ * BATCH;  // 131072

    // 0) zero h buffers + barrier counters
    init_kernel<<<64, 256>>>();

    // 1) encoder: X0[M,256] = input_ids[M,64] @ enc_w[256,64]^T + enc_b
    {
        dim3 grid(M / 64, HID / 32);
        gemm_bias_kernel<<<grid, 128>>>(input_ids, enc_w, enc_b, X0, M, HID, FEAT);
    }

    // 2) persistent pipelined 2-layer LSTM
    {
        size_t smem = (size_t)LSTM_SMEM_FLOATS * sizeof(float);
        cudaFuncSetAttribute(lstm_kernel, cudaFuncAttributeMaxDynamicSharedMemorySize,
                             (int)smem);
        lstm_kernel<<<128, 128, smem>>>(w_ih, w_hh, b_ih, b_hh);
    }

    // 3) decoder: out[M,64] = X2[M,256] @ dec_w[64,256]^T + dec_b
    {
        dim3 grid(M / 64, FEAT / 32);
        gemm_bias_kernel<<<grid, 128>>>(X2, dec_w, dec_b, out, M, FEAT, HID);
    }
}

// round 8
// speedup vs baseline: 1.1763x; 1.1763x over previous
#include <cuda_runtime.h>
#include <cuda_bf16.h>
#include <cstdint>

// Problem constants
#define SEQ   2048
#define BATCH 64
#define FEAT  64
#define HID   256
#define NLAY  2

typedef unsigned long long ull;

// ---------------------------------------------------------------------------
// Device scratch (no allocations allowed)
// ---------------------------------------------------------------------------
__device__ float g_X0[SEQ * BATCH * HID];   // encoder output
__device__ float g_X1[SEQ * BATCH * HID];   // layer0 output
__device__ float g_X2[SEQ * BATCH * HID];   // layer1 output
__device__ float g_Hbuf[NLAY * 2 * BATCH * HID]; // [layer][buf][b*HID + j]
__device__ unsigned g_cnt[NLAY];            // per-layer-group step counters

// ---------------------------------------------------------------------------
// Helpers
// ---------------------------------------------------------------------------
__device__ __forceinline__ ull ffma2(ull a, ull b, ull c) {
    ull d;
    asm("fma.rn.f32x2 %0, %1, %2, %3;" : "=l"(d) : "l"(a), "l"(b), "l"(c));
    return d;
}
__device__ __forceinline__ float sumpair(ull v) {
    float lo, hi;
    asm("mov.b64 {%0, %1}, %2;" : "=f"(lo), "=f"(hi) : "l"(v));
    return lo + hi;
}
__device__ __forceinline__ float sigm(float x) {
    return 1.0f / (1.0f + __expf(-x));
}
__device__ __forceinline__ float tanh_fast(float x) {
    float ax = fabsf(x);
    float t  = __expf(-2.0f * ax);
    float r  = (1.0f - t) / (1.0f + t);
    return copysignf(r, x);
}
__device__ __forceinline__ void cp16(void* dst_smem, const void* src) {
    unsigned d = (unsigned)__cvta_generic_to_shared(dst_smem);
    asm volatile("cp.async.cg.shared.global [%0], [%1], 16;" :: "r"(d), "l"(src));
}
__device__ __forceinline__ unsigned ld_acq(const unsigned* p) {
    unsigned v;
    asm volatile("ld.acquire.gpu.global.u32 %0, [%1];" : "=r"(v) : "l"(p));
    return v;
}
__device__ __forceinline__ void red_rel_add(unsigned* p, unsigned v) {
    asm volatile("red.release.gpu.global.add.u32 [%0], %1;" :: "l"(p), "r"(v) : "memory");
}

// ---------------------------------------------------------------------------
// Init kernel: zero h buffers + barrier counters (runs every launch/replay)
// ---------------------------------------------------------------------------
__global__ void init_kernel() {
    int idx = blockIdx.x * blockDim.x + threadIdx.x;
    if (idx < NLAY) g_cnt[idx] = 0u;
    int stride = gridDim.x * blockDim.x;
    for (int i = idx; i < NLAY * 2 * BATCH * HID; i += stride) g_Hbuf[i] = 0.0f;
}

// ---------------------------------------------------------------------------
// Generic GEMM + bias:  C[M,N] = A[M,K] @ Bw[N,K]^T + bias[N]
// ---------------------------------------------------------------------------
__global__ void __launch_bounds__(128) gemm_bias_kernel(
    const float* __restrict__ A, const float* __restrict__ Bw,
    const float* __restrict__ bias, float* __restrict__ C,
    int M, int N, int K)
{
    __shared__ float As[32][64 + 4];
    __shared__ float Bs[32][32 + 4];

    const int m0 = blockIdx.x * 64;
    const int n0 = blockIdx.y * 32;
    const int tid = threadIdx.x;
    const int tm = tid & 15;
    const int tn = tid >> 4;

    float acc[4][4];
#pragma unroll
    for (int i = 0; i < 4; i++)
#pragma unroll
        for (int jj = 0; jj < 4; jj++) acc[i][jj] = 0.0f;

    for (int kc = 0; kc < K; kc += 32) {
#pragma unroll
        for (int i = 0; i < 4; i++) {
            int idx = tid + i * 128;
            int r = idx >> 3, c4 = idx & 7;
            float4 v = *(const float4*)(A + (size_t)(m0 + r) * K + kc + c4 * 4);
            As[c4 * 4 + 0][r] = v.x;
            As[c4 * 4 + 1][r] = v.y;
            As[c4 * 4 + 2][r] = v.z;
            As[c4 * 4 + 3][r] = v.w;
        }
#pragma unroll
        for (int i = 0; i < 2; i++) {
            int idx = tid + i * 128;
            int r = idx >> 3, c4 = idx & 7;
            float4 v = *(const float4*)(Bw + (size_t)(n0 + r) * K + kc + c4 * 4);
            Bs[c4 * 4 + 0][r] = v.x;
            Bs[c4 * 4 + 1][r] = v.y;
            Bs[c4 * 4 + 2][r] = v.z;
            Bs[c4 * 4 + 3][r] = v.w;
        }
        __syncthreads();

#pragma unroll
        for (int kk = 0; kk < 32; ++kk) {
            float4 a = *(const float4*)&As[kk][tm * 4];
            float4 b = *(const float4*)&Bs[kk][tn * 4];
            float av[4] = {a.x, a.y, a.z, a.w};
            float bv[4] = {b.x, b.y, b.z, b.w};
#pragma unroll
            for (int i = 0; i < 4; i++)
#pragma unroll
                for (int jj = 0; jj < 4; jj++)
                    acc[i][jj] = fmaf(av[i], bv[jj], acc[i][jj]);
        }
        __syncthreads();
    }

    float b0v = bias[n0 + tn * 4 + 0];
    float b1v = bias[n0 + tn * 4 + 1];
    float b2v = bias[n0 + tn * 4 + 2];
    float b3v = bias[n0 + tn * 4 + 3];
#pragma unroll
    for (int i = 0; i < 4; i++) {
        float4 o;
        o.x = acc[i][0] + b0v;
        o.y = acc[i][1] + b1v;
        o.z = acc[i][2] + b2v;
        o.w = acc[i][3] + b3v;
        *(float4*)(C + (size_t)(m0 + tm * 4 + i) * N + n0 + tn * 4) = o;
    }
}

// ---------------------------------------------------------------------------
// Persistent pipelined 2-layer LSTM kernel (v2: 256 threads, K-split).
// Grid = 128 CTAs: [0,64) = layer 0, [64,128) = layer 1.
// CTA tile: 8 hidden-units x 32 batches x 4 gates, K = 512 ([x_t ; h_{t-1}]).
// Threads: j = tid&7, bt = (tid>>3)&15 (2 batches), kh = tid>>7 (K half).
// Warps 0-3 process x-half of K (reads sX), warps 4-7 h-half (reads sH);
// partial sums combined through sRed. Layer-0 CTAs double-buffer sX and
// prefetch x_{t+1} during the epilogue (upper warps), so only h (32 KB)
// is staged on the post-barrier critical path.
// Sync: monotone global counter per layer group, release-红/acquire-poll.
// ---------------------------------------------------------------------------
#define XS    260                      // row stride (floats) for sX / sH
#define XBUF  (32 * XS)                // 8320 floats per x buffer
#define OFF_W    0
#define OFF_X    16384
#define OFF_H    (16384 + 2 * XBUF)    // 33024
#define OFF_RED  (OFF_H + XBUF)       // 41344
#define LSTM_SMEM_FLOATS (OFF_RED + 128 * 12)   // 42880 floats = 171.5 KB

__global__ void __launch_bounds__(256, 1) lstm_kernel(
    const float* __restrict__ w_ih, const float* __restrict__ w_hh,
    const float* __restrict__ b_ih, const float* __restrict__ b_hh)
{
    extern __shared__ float smem[];
    float* sW   = smem + OFF_W;     // [k4][g][j][4] : 16384 floats
    float* sX   = smem + OFF_X;     // 2 x 32 x XS
    float* sH   = smem + OFF_H;     // 32 x XS
    float* sRed = smem + OFF_RED;   // 128 x 12

    const int layer = blockIdx.x >> 6;
    const int c     = blockIdx.x & 63;
    const int j0    = (c & 31) * 8;
    const int b0    = (c >> 5) * 32;
    const int tid   = threadIdx.x;
    const int j     = tid & 7;
    const int bt    = (tid >> 3) & 15;
    const int kh    = tid >> 7;        // 0: x half, 1: h half
    const int bLa   = bt * 2;
    const int bLb   = bt * 2 + 1;

    const float* Xin  = layer ? g_X1 : g_X0;
    float*       Xout = layer ? g_X2 : g_X1;
    float*       Hb   = g_Hbuf + (size_t)layer * (2 * BATCH * HID);
    unsigned*    cs   = &g_cnt[layer];

    // ---- Load & reshuffle W once: dest layout [k4][g][j][4] ----
    for (int idx = tid; idx < 16384; idx += 256) {
        int kk = idx & 3;
        int jj = (idx >> 2) & 7;
        int g  = (idx >> 5) & 3;
        int k4 = idx >> 7;
        int k  = k4 * 4 + kk;
        int r  = g * 256 + j0 + jj;
        float v = (k < 256)
            ? w_ih[((size_t)layer * 1024 + r) * 256 + k]
            : w_hh[((size_t)layer * 1024 + r) * 256 + (k - 256)];
        sW[idx] = v;
    }

    const int jg = j0 + j;
    // b_ih / b_hh shape: (NLAY, 4*HID) -> layer stride 1024
    const float Bi = b_ih[layer * 1024 + 0 * 256 + jg] + b_hh[layer * 1024 + 0 * 256 + jg];
    const float Bf = b_ih[layer * 1024 + 1 * 256 + jg] + b_hh[layer * 1024 + 1 * 256 + jg];
    const float Bg = b_ih[layer * 1024 + 2 * 256 + jg] + b_hh[layer * 1024 + 2 * 256 + jg];
    const float Bo = b_ih[layer * 1024 + 3 * 256 + jg] + b_hh[layer * 1024 + 3 * 256 + jg];

    float cA = 0.0f, cB = 0.0f;

    // ---- prologue: layer 0 stages x_0 into sX buffer 0 ----
    if (layer == 0) {
        const float* xsrc = Xin + (size_t)b0 * HID;  // t = 0
#pragma unroll
        for (int i = 0; i < 8; ++i) {
            int idx = tid + i * 256;
            int row = idx >> 6, col = idx & 63;
            cp16(sX + row * XS + col * 4, xsrc + (size_t)row * HID + col * 4);
        }
        asm volatile("cp.async.commit_group;" ::: "memory");
    }
    __syncthreads();  // W ready

    for (int t = 0; t < SEQ; ++t) {
        // ---- wait: own group finished step t-1; layer1 also needs x_t ----
        if (tid == 0) {
            unsigned tgt = 64u * (unsigned)t;
            while (ld_acq(cs) < tgt) __nanosleep(20);
            if (layer) {
                unsigned tx = 64u * (unsigned)(t + 1);
                while (ld_acq(&g_cnt[0]) < tx) __nanosleep(20);
            }
        }
        __syncthreads();

        // ---- stage post-barrier data ----
        const float* Hprev = Hb + (size_t)((t + 1) & 1) * (BATCH * HID);
        if (layer == 0) {
            // h only (x_t already prefetched)
#pragma unroll
            for (int i = 0; i < 8; ++i) {
                int idx = tid + i * 256;
                int row = idx >> 6, col = idx & 63;
                cp16(sH + row * XS + col * 4,
                     Hprev + (size_t)(b0 + row) * HID + col * 4);
            }
        } else {
            // x_t + h
            const float* xsrc = Xin + ((size_t)t * BATCH + b0) * HID;
#pragma unroll
            for (int i = 0; i < 8; ++i) {
                int idx = tid + i * 256;
                int row = idx >> 6, col = idx & 63;
                cp16(sX + row * XS + col * 4, xsrc + (size_t)row * HID + col * 4);
            }
#pragma unroll
            for (int i = 0; i < 8; ++i) {
                int idx = tid + i * 256;
                int row = idx >> 6, col = idx & 63;
                cp16(sH + row * XS + col * 4,
                     Hprev + (size_t)(b0 + row) * HID + col * 4);
            }
        }
        asm volatile("cp.async.commit_group;" ::: "memory");
        asm volatile("cp.async.wait_group 0;" ::: "memory");
        __syncthreads();

        // ---- compute: this warp's K-half, 4 gates x 2 batches ----
        const float* Xb = sX + (layer == 0 ? ((t & 1) * XBUF) : 0);
        const float* UA = (kh ? sH : Xb) + bLa * XS;
        const float* UB = UA + XS;
        const ulonglong2* Wq = (const ulonglong2*)sW + (size_t)kh * (64 * 32);

        ull aI = 0, aF = 0, aG = 0, aO = 0;
        ull bI = 0, bF = 0, bG = 0, bO = 0;
#pragma unroll 8
        for (int k4 = 0; k4 < 64; ++k4) {
            ulonglong2 ua = *(const ulonglong2*)(UA + k4 * 4);
            ulonglong2 ub = *(const ulonglong2*)(UB + k4 * 4);
            int wb = k4 * 32 + j;
            ulonglong2 wi = Wq[wb];
            ulonglong2 wf = Wq[wb + 8];
            ulonglong2 wg = Wq[wb + 16];
            ulonglong2 wo = Wq[wb + 24];
            aI = ffma2(ua.x, wi.x, aI); aI = ffma2(ua.y, wi.y, aI);
            bI = ffma2(ub.x, wi.x, bI); bI = ffma2(ub.y, wi.y, bI);
            aF = ffma2(ua.x, wf.x, aF); aF = ffma2(ua.y, wf.y, aF);
            bF = ffma2(ub.x, wf.x, bF); bF = ffma2(ub.y, wf.y, bF);
            aG = ffma2(ua.x, wg.x, aG); aG = ffma2(ua.y, wg.y, aG);
            bG = ffma2(ub.x, wg.x, bG); bG = ffma2(ub.y, wg.y, bG);
            aO = ffma2(ua.x, wo.x, aO); aO = ffma2(ua.y, wo.y, aO);
            bO = ffma2(ub.x, wo.x, bO); bO = ffma2(ub.y, wo.y, bO);
        }

        float r0 = sumpair(aI), r1 = sumpair(aF), r2 = sumpair(aG), r3 = sumpair(aO);
        float r4 = sumpair(bI), r5 = sumpair(bF), r6 = sumpair(bG), r7 = sumpair(bO);

        // ---- combine K halves ----
        if (kh) {
            float* p = sRed + (size_t)(tid & 127) * 12;
            *(float4*)p       = make_float4(r0, r1, r2, r3);
            *(float4*)(p + 4) = make_float4(r4, r5, r6, r7);
        }
        __syncthreads();

        if (!kh) {
            const float* p = sRed + (size_t)tid * 12;
            float4 u = *(const float4*)p;
            float4 v = *(const float4*)(p + 4);

            float iv = sigm(r0 + u.x + Bi);
            float fv = sigm(r1 + u.y + Bf);
            float gv = tanh_fast(r2 + u.z + Bg);
            float ov = sigm(r3 + u.w + Bo);
            cA = fv * cA + iv * gv;
            float hA = ov * tanh_fast(cA);

            float iv2 = sigm(r4 + v.x + Bi);
            float fv2 = sigm(r5 + v.y + Bf);
            float gv2 = tanh_fast(r6 + v.z + Bg);
            float ov2 = sigm(r7 + v.w + Bo);
            cB = fv2 * cB + iv2 * gv2;
            float hB = ov2 * tanh_fast(cB);

            float* Hcur = Hb + (size_t)(t & 1) * (BATCH * HID);
            Hcur[(size_t)(b0 + bLa) * HID + jg] = hA;
            Hcur[(size_t)(b0 + bLb) * HID + jg] = hB;
            Xout[((size_t)t * BATCH + b0 + bLa) * HID + jg] = hA;
            Xout[((size_t)t * BATCH + b0 + bLb) * HID + jg] = hB;
        } else if (layer == 0 && t + 1 < SEQ) {
            // ---- upper warps prefetch x_{t+1} during the epilogue ----
            const float* xsrc = Xin + ((size_t)(t + 1) * BATCH + b0) * HID;
            float* xdst = sX + (size_t)((t + 1) & 1) * XBUF;
#pragma unroll
            for (int i = 0; i < 16; ++i) {
                int idx = (tid - 128) + i * 128;
                int row = idx >> 6, col = idx & 63;
                cp16(xdst + row * XS + col * 4, xsrc + (size_t)row * HID + col * 4);
            }
            asm volatile("cp.async.commit_group;" ::: "memory");
        }

        __syncthreads();
        if (tid == 0) red_rel_add(cs, 1u);
    }
}

// ---------------------------------------------------------------------------
// Launch
// ---------------------------------------------------------------------------
extern "C" void kernel_launch(void* const* d_in, const int* in_sizes, int n_in,
                              void* d_out, int out_size)
{
    const float* input_ids = (const float*)d_in[0];
    const float* enc_w     = (const float*)d_in[1];
    const float* enc_b     = (const float*)d_in[2];
    const float* w_ih      = (const float*)d_in[3];
    const float* w_hh      = (const float*)d_in[4];
    const float* b_ih      = (const float*)d_in[5];
    const float* b_hh      = (const float*)d_in[6];
    const float* dec_w     = (const float*)d_in[7];
    const float* dec_b     = (const float*)d_in[8];
    float* out = (float*)d_out;

    void *p0, *p2;
    cudaGetSymbolAddress(&p0, g_X0);
    cudaGetSymbolAddress(&p2, g_X2);
    float* X0 = (float*)p0;
    float* X2 = (float*)p2;

    const int M = SEQ * BATCH;  // 131072

    // 0) zero h buffers + barrier counters
    init_kernel<<<64, 256>>>();

    // 1) encoder: X0[M,256] = input_ids[M,64] @ enc_w[256,64]^T + enc_b
    {
        dim3 grid(M / 64, HID / 32);
        gemm_bias_kernel<<<grid, 128>>>(input_ids, enc_w, enc_b, X0, M, HID, FEAT);
    }

    // 2) persistent pipelined 2-layer LSTM
    {
        size_t smem = (size_t)LSTM_SMEM_FLOATS * sizeof(float);
        cudaFuncSetAttribute(lstm_kernel, cudaFuncAttributeMaxDynamicSharedMemorySize,
                             (int)smem);
        lstm_kernel<<<128, 256, smem>>>(w_ih, w_hh, b_ih, b_hh);
    }

    // 3) decoder: out[M,64] = X2[M,256] @ dec_w[64,256]^T + dec_b
    {
        dim3 grid(M / 64, FEAT / 32);
        gemm_bias_kernel<<<grid, 128>>>(X2, dec_w, dec_b, out, M, FEAT, HID);
    }
}